// round 1
// baseline (speedup 1.0000x reference)
#include <cuda_runtime.h>

// LSTM: B=512, T=1024, F=128, U=256. Fused persistent kernel, batch-parallel.
// Each block owns NB=4 batch rows; h/c state stays on-chip for all 1024 steps.
// Per step, each thread computes 4 consecutive z-columns (of 1024) for all 4 rows:
//   z = bias + x_t @ W + h @ R   (K = 128 + 256 = 384)
// then gate phase: thread u owns unit u (zi=z[u], zf=z[256+u], zo=z[512+u], zg=z[768+u]).
// No inter-block communication needed (recurrence is independent per batch row).

#define BB 512
#define TT 1024
#define FF 128
#define UU 256
#define ZZ 1024   // 4*U
#define NB 4
#define NT 256

#define FMA4(accv, xs, wv)                      \
    accv.x = fmaf((xs), (wv).x, accv.x);        \
    accv.y = fmaf((xs), (wv).y, accv.y);        \
    accv.z = fmaf((xs), (wv).z, accv.z);        \
    accv.w = fmaf((xs), (wv).w, accv.w);

__global__ __launch_bounds__(NT)
void lstm_fused_kernel(const float* __restrict__ x,      // [B, T, F]
                       const float* __restrict__ W,      // [F, 4U]
                       const float* __restrict__ R,      // [U, 4U]
                       const float* __restrict__ bias,   // [4U]
                       const float* __restrict__ h0,     // [B, U]
                       const float* __restrict__ c0,     // [B, U]
                       float* __restrict__ out)          // [B, U]
{
    __shared__ float h_s[NB][UU];
    __shared__ float x_s[NB][FF];
    __shared__ float z_s[NB][ZZ];

    const int tid = threadIdx.x;
    const int b0 = blockIdx.x * NB;

    // c state: thread tid owns unit tid for all NB rows
    float c_reg[NB];
#pragma unroll
    for (int r = 0; r < NB; r++) {
        h_s[r][tid] = h0[(b0 + r) * UU + tid];
        c_reg[r]    = c0[(b0 + r) * UU + tid];
    }

    // bias for this thread's 4 z-columns (constant over time)
    const float4 bv = *reinterpret_cast<const float4*>(bias + 4 * tid);

    // x prefetch: NB*FF = 512 elements/step, 2 per thread
    const int i0 = tid;
    const int i1 = tid + NT;
    const int r0 = i0 / FF, k0 = i0 % FF;
    const int r1 = i1 / FF, k1 = i1 % FF;
    const size_t xoff0 = (size_t)(b0 + r0) * TT * FF + k0;
    const size_t xoff1 = (size_t)(b0 + r1) * TT * FF + k1;

    float xr0 = x[xoff0];
    float xr1 = x[xoff1];

    const float4* Wv = reinterpret_cast<const float4*>(W) + tid;  // row stride ZZ/4
    const float4* Rv = reinterpret_cast<const float4*>(R) + tid;

    __syncthreads();

    for (int t = 0; t < TT; t++) {
        // publish prefetched x_t, then start fetching x_{t+1} (hidden under compute)
        x_s[r0][k0] = xr0;
        x_s[r1][k1] = xr1;
        __syncthreads();

        if (t + 1 < TT) {
            xr0 = x[xoff0 + (size_t)(t + 1) * FF];
            xr1 = x[xoff1 + (size_t)(t + 1) * FF];
        }

        float4 acc0 = bv, acc1 = bv, acc2 = bv, acc3 = bv;

        // input projection part: K = 128 over x_s / W
#pragma unroll 2
        for (int k4 = 0; k4 < FF / 4; k4++) {
            const float4 w0 = Wv[(4 * k4 + 0) * (ZZ / 4)];
            const float4 w1 = Wv[(4 * k4 + 1) * (ZZ / 4)];
            const float4 w2 = Wv[(4 * k4 + 2) * (ZZ / 4)];
            const float4 w3 = Wv[(4 * k4 + 3) * (ZZ / 4)];

            float4 xv;
            xv = *reinterpret_cast<const float4*>(&x_s[0][4 * k4]);
            FMA4(acc0, xv.x, w0) FMA4(acc0, xv.y, w1) FMA4(acc0, xv.z, w2) FMA4(acc0, xv.w, w3)
            xv = *reinterpret_cast<const float4*>(&x_s[1][4 * k4]);
            FMA4(acc1, xv.x, w0) FMA4(acc1, xv.y, w1) FMA4(acc1, xv.z, w2) FMA4(acc1, xv.w, w3)
            xv = *reinterpret_cast<const float4*>(&x_s[2][4 * k4]);
            FMA4(acc2, xv.x, w0) FMA4(acc2, xv.y, w1) FMA4(acc2, xv.z, w2) FMA4(acc2, xv.w, w3)
            xv = *reinterpret_cast<const float4*>(&x_s[3][4 * k4]);
            FMA4(acc3, xv.x, w0) FMA4(acc3, xv.y, w1) FMA4(acc3, xv.z, w2) FMA4(acc3, xv.w, w3)
        }

        // recurrent part: K = 256 over h_s / R
#pragma unroll 2
        for (int k4 = 0; k4 < UU / 4; k4++) {
            const float4 w0 = Rv[(4 * k4 + 0) * (ZZ / 4)];
            const float4 w1 = Rv[(4 * k4 + 1) * (ZZ / 4)];
            const float4 w2 = Rv[(4 * k4 + 2) * (ZZ / 4)];
            const float4 w3 = Rv[(4 * k4 + 3) * (ZZ / 4)];

            float4 hv;
            hv = *reinterpret_cast<const float4*>(&h_s[0][4 * k4]);
            FMA4(acc0, hv.x, w0) FMA4(acc0, hv.y, w1) FMA4(acc0, hv.z, w2) FMA4(acc0, hv.w, w3)
            hv = *reinterpret_cast<const float4*>(&h_s[1][4 * k4]);
            FMA4(acc1, hv.x, w0) FMA4(acc1, hv.y, w1) FMA4(acc1, hv.z, w2) FMA4(acc1, hv.w, w3)
            hv = *reinterpret_cast<const float4*>(&h_s[2][4 * k4]);
            FMA4(acc2, hv.x, w0) FMA4(acc2, hv.y, w1) FMA4(acc2, hv.z, w2) FMA4(acc2, hv.w, w3)
            hv = *reinterpret_cast<const float4*>(&h_s[3][4 * k4]);
            FMA4(acc3, hv.x, w0) FMA4(acc3, hv.y, w1) FMA4(acc3, hv.z, w2) FMA4(acc3, hv.w, w3)
        }

        *reinterpret_cast<float4*>(&z_s[0][4 * tid]) = acc0;
        *reinterpret_cast<float4*>(&z_s[1][4 * tid]) = acc1;
        *reinterpret_cast<float4*>(&z_s[2][4 * tid]) = acc2;
        *reinterpret_cast<float4*>(&z_s[3][4 * tid]) = acc3;
        __syncthreads();

        // gate phase: thread tid = unit tid; split order i, f, o, g
#pragma unroll
        for (int r = 0; r < NB; r++) {
            const float zi = z_s[r][tid];
            const float zf = z_s[r][UU + tid];
            const float zo = z_s[r][2 * UU + tid];
            const float zg = z_s[r][3 * UU + tid];
            const float ig = 1.0f / (1.0f + __expf(-zi));
            const float fg = 1.0f / (1.0f + __expf(-zf));
            const float og = 1.0f / (1.0f + __expf(-zo));
            const float gg = tanhf(zg);
            const float c  = fmaf(fg, c_reg[r], ig * gg);
            c_reg[r] = c;
            h_s[r][tid] = og * tanhf(c);
        }
        __syncthreads();
    }

    // final hidden state
#pragma unroll
    for (int r = 0; r < NB; r++)
        out[(b0 + r) * UU + tid] = h_s[r][tid];
}

extern "C" void kernel_launch(void* const* d_in, const int* in_sizes, int n_in,
                              void* d_out, int out_size) {
    const float* x    = (const float*)d_in[0];
    const float* W    = (const float*)d_in[1];
    const float* R    = (const float*)d_in[2];
    const float* bias = (const float*)d_in[3];
    const float* h0   = (const float*)d_in[4];
    const float* c0   = (const float*)d_in[5];
    float* out = (float*)d_out;

    lstm_fused_kernel<<<BB / NB, NT>>>(x, W, R, bias, h0, c0, out);
}

// round 2
// speedup vs baseline: 2.4520x; 2.4520x over previous
#include <cuda_runtime.h>

// LSTM B=512, T=1024, F=128, U=256.
// Phase 0 (prep): permute W,R,bias columns  P = 4*u + g  (gate-interleaved).
// Phase 1 (gemm): xk[t][b][P] = bias[P] + sum_f x[b][t][f] * W[f][P]  (2 GiB scratch)
// Phase 2 (recur): 128 persistent CTAs, R-slice stationary in smem,
//                  per-step grid barrier, h double-buffered in global.
// fp32 math throughout via packed fma.rn.f32x2 (sm_103a).

#define T_STEPS 1024
#define B_SIZE  512
#define F_IN    128
#define U_HID   256
#define Z4      1024

#define P2_CTAS 128
#define HP      260                      // padded h_s row (floats), 16B aligned
#define G1_SMEM ((128 * 132 + 128 * 128) * 4)
#define G2_SMEM ((256 * 128 + 32 * HP) * 4)

// ---- device scratch (static allocation is the sanctioned path) ----
__device__ float g_Wp[F_IN * Z4];
__device__ float g_Rp[U_HID * Z4];
__device__ float g_bp[Z4];
__device__ float g_xk[(size_t)T_STEPS * B_SIZE * Z4];   // 2 GiB
__device__ float g_hbuf[2][B_SIZE * U_HID];
__device__ unsigned g_bar_cnt = 0;
__device__ unsigned g_bar_flag = 0;

// ---- packed f32x2 helpers ----
__device__ __forceinline__ unsigned long long pack2(float v) {
    unsigned long long r;
    asm("mov.b64 %0, {%1, %1};" : "=l"(r) : "f"(v));
    return r;
}
__device__ __forceinline__ void ffma2(unsigned long long& d,
                                      unsigned long long a,
                                      unsigned long long b) {
    asm("fma.rn.f32x2 %0, %1, %2, %0;" : "+l"(d) : "l"(a), "l"(b));
}
__device__ __forceinline__ void unpack2(unsigned long long v, float& lo, float& hi) {
    asm("mov.b64 {%0, %1}, %2;" : "=f"(lo), "=f"(hi) : "l"(v));
}
__device__ __forceinline__ float sig_fast(float x) {
    return __fdividef(1.0f, 1.0f + __expf(-x));
}
__device__ __forceinline__ float tanh_acc(float x) {
    return __fdividef(2.0f, 1.0f + __expf(-2.0f * x)) - 1.0f;
}

// ================= phase 0: permute weights =================
__global__ void lstm_prep(const float* __restrict__ W,
                          const float* __restrict__ R,
                          const float* __restrict__ bias) {
    int i = blockIdx.x * blockDim.x + threadIdx.x;
    if (i < F_IN * Z4) {
        int f = i >> 10, P = i & 1023;
        g_Wp[i] = W[(f << 10) + ((P & 3) << 8) + (P >> 2)];
    } else if (i < (F_IN + U_HID) * Z4) {
        int j = i - F_IN * Z4;
        int k = j >> 10, P = j & 1023;
        g_Rp[j] = R[(k << 10) + ((P & 3) << 8) + (P >> 2)];
    } else if (i < (F_IN + U_HID) * Z4 + Z4) {
        int P = i - (F_IN + U_HID) * Z4;
        g_bp[P] = bias[((P & 3) << 8) + (P >> 2)];
    }
}

// ================= phase 1: xk = x @ W_perm + bias_perm =================
// grid (8, 4096): blockIdx.x = col tile (128 cols), blockIdx.y = 128-row tile of x.
__global__ __launch_bounds__(256, 1)
void lstm_gemm_x(const float* __restrict__ x) {
    extern __shared__ float sm1[];
    float* x_s = sm1;               // [128][132]  (pad: rows differing by 1 hit diff banks)
    float* W_s = sm1 + 128 * 132;   // [128][128]
    const int tid = threadIdx.x;
    const int tx = tid & 15, ty = tid >> 4;   // ty 0..15
    const int gy = blockIdx.x;                // 0..7
    const int gx = blockIdx.y;                // 0..4095

    const float* xg = x + (size_t)gx * 128 * F_IN;
    for (int i = tid; i < 128 * 128 / 4; i += 256) {
        int r = i >> 5, f4 = i & 31;
        *(float4*)&x_s[r * 132 + f4 * 4] = ((const float4*)xg)[i];
    }
    for (int i = tid; i < 128 * 128 / 4; i += 256) {
        int k = i >> 5, c4 = i & 31;
        *(float4*)&W_s[k * 128 + c4 * 4] =
            *(const float4*)&g_Wp[k * Z4 + gy * 128 + c4 * 4];
    }

    unsigned long long acc[8][4];
    {
        const ulonglong2 b0 = *(const ulonglong2*)&g_bp[gy * 128 + tx * 8];
        const ulonglong2 b1 = *(const ulonglong2*)&g_bp[gy * 128 + tx * 8 + 4];
#pragma unroll
        for (int r = 0; r < 8; r++) {
            acc[r][0] = b0.x; acc[r][1] = b0.y; acc[r][2] = b1.x; acc[r][3] = b1.y;
        }
    }
    __syncthreads();

#pragma unroll 4
    for (int k = 0; k < 128; k++) {
        const ulonglong2 w0 = *(const ulonglong2*)&W_s[k * 128 + tx * 8];
        const ulonglong2 w1 = *(const ulonglong2*)&W_s[k * 128 + tx * 8 + 4];
#pragma unroll
        for (int r = 0; r < 8; r++) {
            const unsigned long long a = pack2(x_s[(ty + 16 * r) * 132 + k]);
            ffma2(acc[r][0], a, w0.x);
            ffma2(acc[r][1], a, w0.y);
            ffma2(acc[r][2], a, w1.x);
            ffma2(acc[r][3], a, w1.y);
        }
    }

    // epilogue: row m = gx*128 + ty + 16*r ;  b = m>>10 (const per tile), t = m&1023
    const int bb = gx >> 3;
    const int t0 = (gx & 7) * 128;
#pragma unroll
    for (int r = 0; r < 8; r++) {
        const int t = t0 + ty + 16 * r;
        float* dst = &g_xk[(((size_t)t * B_SIZE) + bb) * Z4 + gy * 128 + tx * 8];
        *(ulonglong2*)dst       = make_ulonglong2(acc[r][0], acc[r][1]);
        *(ulonglong2*)(dst + 4) = make_ulonglong2(acc[r][2], acc[r][3]);
    }
}

// ================= phase 2: persistent recurrence =================
__device__ __forceinline__ void grid_barrier(unsigned sense) {
    __syncthreads();
    if (threadIdx.x == 0) {
        __threadfence();
        unsigned arrived = atomicAdd(&g_bar_cnt, 1);
        if (arrived == P2_CTAS - 1) {
            g_bar_cnt = 0;
            __threadfence();
            atomicExch(&g_bar_flag, sense);
        } else {
            while (*(volatile unsigned*)&g_bar_flag != sense) { }
            __threadfence();
        }
    }
    __syncthreads();
}

__global__ __launch_bounds__(128, 1)
void lstm_recur(const float* __restrict__ h0, const float* __restrict__ c0,
                float* __restrict__ out) {
    extern __shared__ float sm2[];
    float* R_s = sm2;                 // [256][128]
    float* h_s = sm2 + 256 * 128;     // [32][HP]
    const int tid = threadIdx.x;
    const int tx = tid & 15, ty = tid >> 4;   // tx 0..15, ty 0..7
    const int ci = blockIdx.x >> 3;           // batch tile 0..15
    const int cj = blockIdx.x & 7;            // unit tile 0..7
    const int b_base = ci * 32;
    const int col0 = cj * 128 + tx * 8;

    // stationary R slice: [256 k][128 cols]
    for (int i = tid; i < 256 * 128 / 4; i += 128) {
        int k = i >> 5, c4 = i & 31;
        *(float4*)&R_s[k * 128 + c4 * 4] =
            *(const float4*)&g_Rp[k * Z4 + cj * 128 + c4 * 4];
    }

    // c state: thread owns 4 rows x 2 units
    float creg[4][2];
#pragma unroll
    for (int r = 0; r < 4; r++)
#pragma unroll
        for (int uu = 0; uu < 2; uu++)
            creg[r][uu] = c0[(b_base + ty * 4 + r) * U_HID + cj * 32 + tx * 2 + uu];

    unsigned sense = 0;

    for (int t = 0; t < T_STEPS; t++) {
        // stage full h (256 units) for own 32 batch rows
        const float* hsrc = (t == 0) ? (h0 + b_base * U_HID)
                                     : (g_hbuf[t & 1] + b_base * U_HID);
        for (int i = tid; i < 32 * 64; i += 128) {
            int r = i >> 6, c4 = i & 63;
            *(float4*)&h_s[r * HP + c4 * 4] = *(const float4*)&hsrc[r * U_HID + c4 * 4];
        }

        // init acc from xk (streamed once from DRAM)
        unsigned long long acc[4][4];
        const float* xkp = &g_xk[(((size_t)t * B_SIZE) + b_base) * Z4 + col0];
#pragma unroll
        for (int r = 0; r < 4; r++) {
            const size_t ro = (size_t)(ty * 4 + r) * Z4;
            const ulonglong2 v0 = *(const ulonglong2*)(xkp + ro);
            const ulonglong2 v1 = *(const ulonglong2*)(xkp + ro + 4);
            acc[r][0] = v0.x; acc[r][1] = v0.y; acc[r][2] = v1.x; acc[r][3] = v1.y;
        }
        __syncthreads();   // h_s (and first-iter R_s) ready

        // z += h @ R : K=256, per-thread 4 rows x 8 cols, packed f32x2
#pragma unroll 2
        for (int k4 = 0; k4 < 64; k4++) {
            float4 hv[4];
#pragma unroll
            for (int r = 0; r < 4; r++)
                hv[r] = *(const float4*)&h_s[(ty * 4 + r) * HP + k4 * 4];
#pragma unroll
            for (int kk = 0; kk < 4; kk++) {
                const float* rrow = &R_s[(k4 * 4 + kk) * 128 + tx * 8];
                const ulonglong2 w0 = *(const ulonglong2*)rrow;
                const ulonglong2 w1 = *(const ulonglong2*)(rrow + 4);
#pragma unroll
                for (int r = 0; r < 4; r++) {
                    const unsigned long long a = pack2(((const float*)&hv[r])[kk]);
                    ffma2(acc[r][0], a, w0.x);
                    ffma2(acc[r][1], a, w0.y);
                    ffma2(acc[r][2], a, w1.x);
                    ffma2(acc[r][3], a, w1.y);
                }
            }
        }

        // gates: cols are (u,u+1) x (i,f,o,g) -> all local
        float* hdst = (t + 1 < T_STEPS) ? &g_hbuf[(t + 1) & 1][0] : out;
#pragma unroll
        for (int r = 0; r < 4; r++) {
            float h2[2];
#pragma unroll
            for (int uu = 0; uu < 2; uu++) {
                float zi, zf, zo, zg;
                unpack2(acc[r][2 * uu],     zi, zf);
                unpack2(acc[r][2 * uu + 1], zo, zg);
                const float ig = sig_fast(zi);
                const float fg = sig_fast(zf);
                const float og = sig_fast(zo);
                const float gg = tanh_acc(zg);
                const float c  = fmaf(fg, creg[r][uu], ig * gg);
                creg[r][uu] = c;
                h2[uu] = og * tanh_acc(c);
            }
            *(float2*)&hdst[(b_base + ty * 4 + r) * U_HID + cj * 32 + tx * 2] =
                make_float2(h2[0], h2[1]);
        }

        grid_barrier(sense ^= 1);   // even count (1024) -> flag returns to 0 for replay
    }
}

extern "C" void kernel_launch(void* const* d_in, const int* in_sizes, int n_in,
                              void* d_out, int out_size) {
    const float* x    = (const float*)d_in[0];
    const float* W    = (const float*)d_in[1];
    const float* R    = (const float*)d_in[2];
    const float* bias = (const float*)d_in[3];
    const float* h0   = (const float*)d_in[4];
    const float* c0   = (const float*)d_in[5];
    float* out = (float*)d_out;

    cudaFuncSetAttribute(lstm_gemm_x, cudaFuncAttributeMaxDynamicSharedMemorySize, G1_SMEM);
    cudaFuncSetAttribute(lstm_recur,  cudaFuncAttributeMaxDynamicSharedMemorySize, G2_SMEM);

    const int prep_total = (F_IN + U_HID) * Z4 + Z4;
    lstm_prep<<<(prep_total + 255) / 256, 256>>>(W, R, bias);
    lstm_gemm_x<<<dim3(8, 4096), 256, G1_SMEM>>>(x);
    lstm_recur<<<P2_CTAS, 128, G2_SMEM>>>(h0, c0, out);
}

// round 5
// speedup vs baseline: 5.0766x; 2.0704x over previous
#include <cuda_runtime.h>
#include <cuda_bf16.h>

typedef unsigned int u32;
typedef unsigned short u16;

#define TT 1024
#define BB 512
#define FI 128
#define UU 256
#define PP 1024        // 4*U, permuted: block b16=P>>4, c=P&15: c<8 -> i/f, c>=8 -> o/g
#define RC_CTAS 128

// ---------------- device scratch ----------------
__device__ __nv_bfloat16 g_WT_hi[PP * FI], g_WT_lo[PP * FI];  // [P][f], k-contig
__device__ __nv_bfloat16 g_RT_hi[PP * UU], g_RT_lo[PP * UU];  // [P][k], k-contig
__device__ __nv_bfloat16 g_h_hi[BB * UU], g_h_lo[BB * UU];
__device__ float g_bp[PP];
__device__ float g_xk[(size_t)TT * BB * PP];                  // [(t*512+b)*1024+P]
__device__ unsigned g_bar_cnt = 0, g_bar_flag = 0;

// ---------------- helpers ----------------
__device__ __forceinline__ u32 s2u(const void* p) {
    u32 a;
    asm("{ .reg .u64 t; cvta.to.shared.u64 t, %1; cvt.u32.u64 %0, t; }" : "=r"(a) : "l"(p));
    return a;
}
__device__ __forceinline__ void ldsm4(u32 addr, u32* r) {
    asm volatile("ldmatrix.sync.aligned.m8n8.x4.shared.b16 {%0,%1,%2,%3}, [%4];"
                 : "=r"(r[0]), "=r"(r[1]), "=r"(r[2]), "=r"(r[3]) : "r"(addr));
}
__device__ __forceinline__ void mma16816(float* c, const u32* a, u32 b0, u32 b1) {
    asm volatile(
        "mma.sync.aligned.m16n8k16.row.col.f32.bf16.bf16.f32 "
        "{%0,%1,%2,%3},{%4,%5,%6,%7},{%8,%9},{%0,%1,%2,%3};"
        : "+f"(c[0]), "+f"(c[1]), "+f"(c[2]), "+f"(c[3])
        : "r"(a[0]), "r"(a[1]), "r"(a[2]), "r"(a[3]), "r"(b0), "r"(b1));
}
__device__ __forceinline__ float sig_fast(float x) {
    return __fdividef(1.0f, 1.0f + __expf(-x));
}
__device__ __forceinline__ float tanh_acc(float x) {
    return __fdividef(2.0f, 1.0f + __expf(-2.0f * x)) - 1.0f;
}
__device__ __forceinline__ void bf_split(float v, u16& hi, u16& lo) {
    __nv_bfloat16 h = __float2bfloat16(v);
    hi = __bfloat16_as_ushort(h);
    lo = __bfloat16_as_ushort(__float2bfloat16(v - __bfloat162float(h)));
}
__device__ __forceinline__ int origcol(int P) {   // permuted col -> keras col
    int blk = P >> 4, c = P & 15;
    int u = 4 * blk + ((c >> 1) & 3);
    int g = ((c >> 3) << 1) | (c & 1);            // 0:i 1:f 2:o 3:g
    return g * UU + u;
}

// ================= prep =================
__global__ void lstm_prep(const float* __restrict__ W, const float* __restrict__ R,
                          const float* __restrict__ bias, const float* __restrict__ h0) {
    int i = blockIdx.x * blockDim.x + threadIdx.x;
    if (i < PP * FI) {
        int P = i >> 7, f = i & 127;
        u16 h, l; bf_split(W[f * PP + origcol(P)], h, l);
        g_WT_hi[i] = __ushort_as_bfloat16(h); g_WT_lo[i] = __ushort_as_bfloat16(l);
    } else if (i < PP * FI + PP * UU) {
        int j = i - PP * FI;
        int P = j >> 8, k = j & 255;
        u16 h, l; bf_split(R[k * PP + origcol(P)], h, l);
        g_RT_hi[j] = __ushort_as_bfloat16(h); g_RT_lo[j] = __ushort_as_bfloat16(l);
    } else if (i < PP * FI + PP * UU + PP) {
        int P = i - PP * FI - PP * UU;
        g_bp[P] = bias[origcol(P)];
    } else if (i < PP * FI + PP * UU + PP + BB * UU) {
        int j = i - PP * FI - PP * UU - PP;
        u16 h, l; bf_split(h0[j], h, l);
        g_h_hi[j] = __ushort_as_bfloat16(h); g_h_lo[j] = __ushort_as_bfloat16(l);
    }
}

// ================= phase 1: xk = x @ W =================
// CTA tile: 128 rows (t) x 64 cols (P), K=128. grid (4096, 16).
// smem: A pad stride 136 bf16 (272B), B stride 136.
#define G_AHI 0
#define G_ALO 34816
#define G_BHI 69632
#define G_BLO 87040
#define G_SMEM (104448 + 32)

__global__ __launch_bounds__(256, 1) void lstm_gemm_x(const float* __restrict__ x) {
    extern __shared__ char sb[];
    const u32 sbase = s2u(sb);
    const int tid = threadIdx.x;
    const int w = tid >> 5, lane = tid & 31;
    const int b = blockIdx.x >> 3;
    const int t0 = (blockIdx.x & 7) << 7;
    const int n0 = blockIdx.y * 64;
    const int mchunk = w & 3;          // 4 x 32 rows
    const int nchunk = w >> 2;         // 2 x 32 cols
    const int q = lane & 3;

    // stage A: x rows (b, t0..t0+127) -> bf16 split, padded 272B rows
    for (int it = 0; it < 16; it++) {
        int idx4 = tid + it * 256;             // 4096 float4
        int row = idx4 >> 5, f4 = idx4 & 31;
        float4 v = *(const float4*)&x[((size_t)b * TT + t0 + row) * FI + f4 * 4];
        u16 h0_, l0_, h1_, l1_, h2_, l2_, h3_, l3_;
        bf_split(v.x, h0_, l0_); bf_split(v.y, h1_, l1_);
        bf_split(v.z, h2_, l2_); bf_split(v.w, h3_, l3_);
        uint2 hv = make_uint2((u32)h0_ | ((u32)h1_ << 16), (u32)h2_ | ((u32)h3_ << 16));
        uint2 lv = make_uint2((u32)l0_ | ((u32)l1_ << 16), (u32)l2_ | ((u32)l3_ << 16));
        *(uint2*)(sb + G_AHI + row * 272 + f4 * 8) = hv;
        *(uint2*)(sb + G_ALO + row * 272 + f4 * 8) = lv;
    }
    // stage B: W^T slice [64 n][128 k]
    for (int it = 0; it < 4; it++) {
        int idx4 = tid + it * 256;             // 1024 uint4
        int n = idx4 >> 4, ku = idx4 & 15;
        *(uint4*)(sb + G_BHI + n * 272 + ku * 16) =
            *(const uint4*)&g_WT_hi[(n0 + n) * FI + ku * 8];
        *(uint4*)(sb + G_BLO + n * 272 + ku * 16) =
            *(const uint4*)&g_WT_lo[(n0 + n) * FI + ku * 8];
    }
    __syncthreads();

    // ldmatrix lane addresses
    const int rA = mchunk * 32 + (lane & 7) + 8 * ((lane >> 3) & 1);
    const int cA = 8 * ((lane >> 4) & 1);
    const u32 aH = sbase + G_AHI + rA * 272 + cA * 2;
    const u32 aL = sbase + G_ALO + rA * 272 + cA * 2;
    const int rB = nchunk * 32 + (lane & 7) + 8 * ((lane >> 4) & 1);
    const int cB = 8 * ((lane >> 3) & 1);
    const u32 bH = sbase + G_BHI + rB * 272 + cB * 2;
    const u32 bL = sbase + G_BLO + rB * 272 + cB * 2;

    // B_hi fragments in registers: [8 k16][8] (two n16 halves)
    u32 bh[8][8];
#pragma unroll
    for (int k = 0; k < 8; k++) {
        ldsm4(bH + k * 32, &bh[k][0]);
        ldsm4(bH + 16 * 272 + k * 32, &bh[k][4]);
    }

    float C[2][4][4];
#pragma unroll
    for (int m = 0; m < 2; m++)
#pragma unroll
        for (int n = 0; n < 4; n++)
#pragma unroll
            for (int r = 0; r < 4; r++) C[m][n][r] = 0.0f;

    // loop1: aH x (bH + bL)
#pragma unroll
    for (int k = 0; k < 8; k++) {
        u32 a0[4], a1[4], bl0[4], bl1[4];
        ldsm4(aH + k * 32, a0);
        ldsm4(aH + 16 * 272 + k * 32, a1);
        ldsm4(bL + k * 32, bl0);
        ldsm4(bL + 16 * 272 + k * 32, bl1);
#pragma unroll
        for (int n = 0; n < 4; n++) {
            mma16816(C[0][n], a0, bh[k][2 * n], bh[k][2 * n + 1]);
            mma16816(C[1][n], a1, bh[k][2 * n], bh[k][2 * n + 1]);
        }
        mma16816(C[0][0], a0, bl0[0], bl0[1]);
        mma16816(C[0][1], a0, bl0[2], bl0[3]);
        mma16816(C[0][2], a0, bl1[0], bl1[1]);
        mma16816(C[0][3], a0, bl1[2], bl1[3]);
        mma16816(C[1][0], a1, bl0[0], bl0[1]);
        mma16816(C[1][1], a1, bl0[2], bl0[3]);
        mma16816(C[1][2], a1, bl1[0], bl1[1]);
        mma16816(C[1][3], a1, bl1[2], bl1[3]);
    }
    // loop2: aL x bH
#pragma unroll
    for (int k = 0; k < 8; k++) {
        u32 a0[4], a1[4];
        ldsm4(aL + k * 32, a0);
        ldsm4(aL + 16 * 272 + k * 32, a1);
#pragma unroll
        for (int n = 0; n < 4; n++) {
            mma16816(C[0][n], a0, bh[k][2 * n], bh[k][2 * n + 1]);
            mma16816(C[1][n], a1, bh[k][2 * n], bh[k][2 * n + 1]);
        }
    }

    // epilogue: rows trow = mchunk*32 + {0,8,16,24} + lane/4 ; cols nchunk*32 + 8n + 2q
#pragma unroll
    for (int mi = 0; mi < 4; mi++) {
        const int trow = t0 + mchunk * 32 + 8 * mi + (lane >> 2);
        float* dst = &g_xk[(((size_t)trow * BB) + b) * PP + n0 + nchunk * 32];
        const int m2 = mi >> 1, rr = (mi & 1) * 2;
#pragma unroll
        for (int n = 0; n < 4; n++)
            *(float2*)(dst + 8 * n + 2 * q) = make_float2(C[m2][n][rr], C[m2][n][rr + 1]);
    }
}

// ================= phase 2: persistent recurrence =================
// 128 CTAs: mt = blk>>4 (64 batch rows), nt = blk&15 (64 P cols). K=256.
// smem: A [64][264] bf16 hi/lo (528B stride), B same.
#define R_AHI 0
#define R_ALO 33792
#define R_BHI 67584
#define R_BLO 101376
#define R_SMEM (135168 + 32)

__device__ __forceinline__ void grid_barrier(unsigned sense) {
    __syncthreads();
    if (threadIdx.x == 0) {
        __threadfence();
        unsigned arrived = atomicAdd(&g_bar_cnt, 1);
        if (arrived == RC_CTAS - 1) {
            g_bar_cnt = 0;
            __threadfence();
            atomicExch(&g_bar_flag, sense);
        } else {
            while (*(volatile unsigned*)&g_bar_flag != sense) { }
            __threadfence();
        }
    }
    __syncthreads();
}

__global__ __launch_bounds__(256, 1) void lstm_recur(const float* __restrict__ c0,
                                                     float* __restrict__ out) {
    extern __shared__ char sb[];
    const u32 sbase = s2u(sb);
    const int tid = threadIdx.x;
    const int w = tid >> 5, lane = tid & 31;
    const int b_base = (blockIdx.x >> 4) * 64;
    const int nt = blockIdx.x & 15;
    const int n0 = nt * 64;
    const int mchunk = w & 1;          // 2 x 32 rows
    const int nchunk = w >> 1;         // 4 x 16 cols
    const int q = lane & 3;

    // stationary B: R^T slice [64 n][256 k] hi/lo
    for (int it = 0; it < 8; it++) {
        int idx4 = tid + it * 256;             // 2048 uint4 per array
        int n = idx4 >> 5, ku = idx4 & 31;
        *(uint4*)(sb + R_BHI + n * 528 + ku * 16) =
            *(const uint4*)&g_RT_hi[(n0 + n) * UU + ku * 8];
        *(uint4*)(sb + R_BLO + n * 528 + ku * 16) =
            *(const uint4*)&g_RT_lo[(n0 + n) * UU + ku * 8];
    }
    __syncthreads();

    // lane addresses
    const int rA = mchunk * 32 + (lane & 7) + 8 * ((lane >> 3) & 1);
    const int cA = 8 * ((lane >> 4) & 1);
    const u32 aH = sbase + R_AHI + rA * 528 + cA * 2;
    const u32 aL = sbase + R_ALO + rA * 528 + cA * 2;
    const int rB = nchunk * 16 + (lane & 7) + 8 * ((lane >> 4) & 1);
    const int cB = 8 * ((lane >> 3) & 1);
    const u32 bHa = sbase + R_BHI + rB * 528 + cB * 2;
    const u32 bLa = sbase + R_BLO + rB * 528 + cB * 2;

    // B_hi fragments resident in registers for all 1024 steps: [16 k16][4]
    u32 bh[16][4];
#pragma unroll
    for (int k = 0; k < 16; k++) ldsm4(bHa + k * 32, bh[k]);

    // thread owns unit u for 4 batch rows
    const int B16 = nt * 4 + nchunk;
    const int u = 4 * B16 + q;
    const int row_l = lane >> 2;
    float c_reg[4];
#pragma unroll
    for (int mi = 0; mi < 4; mi++)
        c_reg[mi] = c0[(b_base + mchunk * 32 + 8 * mi + row_l) * UU + u];
    const float2 b_if = *(const float2*)&g_bp[16 * B16 + 2 * q];
    const float2 b_og = *(const float2*)&g_bp[16 * B16 + 8 + 2 * q];

    unsigned sense = 0;

    for (int t = 0; t < TT; t++) {
        // stage h -> A smem (hi/lo)
        for (int it = 0; it < 8; it++) {
            int idx4 = tid + it * 256;
            int r = idx4 >> 5, ku = idx4 & 31;
            *(uint4*)(sb + R_AHI + r * 528 + ku * 16) =
                *(const uint4*)&g_h_hi[(b_base + r) * UU + ku * 8];
            *(uint4*)(sb + R_ALO + r * 528 + ku * 16) =
                *(const uint4*)&g_h_lo[(b_base + r) * UU + ku * 8];
        }
        __syncthreads();

        // prefetch xk for this thread's 16 z-values (in flight under the mma loops)
        float2 xk_if[4], xk_og[4];
#pragma unroll
        for (int mi = 0; mi < 4; mi++) {
            const float* xp = &g_xk[(((size_t)t * BB) + b_base + mchunk * 32 + 8 * mi + row_l) * PP
                                    + 16 * B16];
            xk_if[mi] = *(const float2*)(xp + 2 * q);
            xk_og[mi] = *(const float2*)(xp + 8 + 2 * q);
        }

        float C[2][2][4];
#pragma unroll
        for (int m = 0; m < 2; m++)
#pragma unroll
            for (int n = 0; n < 2; n++)
#pragma unroll
                for (int r = 0; r < 4; r++) C[m][n][r] = 0.0f;

        // loop1: aH x (bH_regs + bL)
#pragma unroll
        for (int k = 0; k < 16; k++) {
            u32 a0[4], a1[4], bl[4];
            ldsm4(aH + k * 32, a0);
            ldsm4(aH + 16 * 528 + k * 32, a1);
            ldsm4(bLa + k * 32, bl);
            mma16816(C[0][0], a0, bh[k][0], bh[k][1]);
            mma16816(C[0][1], a0, bh[k][2], bh[k][3]);
            mma16816(C[1][0], a1, bh[k][0], bh[k][1]);
            mma16816(C[1][1], a1, bh[k][2], bh[k][3]);
            mma16816(C[0][0], a0, bl[0], bl[1]);
            mma16816(C[0][1], a0, bl[2], bl[3]);
            mma16816(C[1][0], a1, bl[0], bl[1]);
            mma16816(C[1][1], a1, bl[2], bl[3]);
        }
        // loop2: aL x bH_regs
#pragma unroll
        for (int k = 0; k < 16; k++) {
            u32 a0[4], a1[4];
            ldsm4(aL + k * 32, a0);
            ldsm4(aL + 16 * 528 + k * 32, a1);
            mma16816(C[0][0], a0, bh[k][0], bh[k][1]);
            mma16816(C[0][1], a0, bh[k][2], bh[k][3]);
            mma16816(C[1][0], a1, bh[k][0], bh[k][1]);
            mma16816(C[1][1], a1, bh[k][2], bh[k][3]);
        }

        // gates: thread has all 4 gates of unit u for 4 rows
#pragma unroll
        for (int mi = 0; mi < 4; mi++) {
            const int m2 = mi >> 1, rr = (mi & 1) * 2;
            const float zi = C[m2][0][rr]     + xk_if[mi].x + b_if.x;
            const float zf = C[m2][0][rr + 1] + xk_if[mi].y + b_if.y;
            const float zo = C[m2][1][rr]     + xk_og[mi].x + b_og.x;
            const float zg = C[m2][1][rr + 1] + xk_og[mi].y + b_og.y;
            const float ig = sig_fast(zi);
            const float fg = sig_fast(zf);
            const float og = sig_fast(zo);
            const float gg = tanh_acc(zg);
            const float c = fmaf(fg, c_reg[mi], ig * gg);
            c_reg[mi] = c;
            const float h = og * tanh_acc(c);
            const int br = b_base + mchunk * 32 + 8 * mi + row_l;
            u16 hh, hl; bf_split(h, hh, hl);
            g_h_hi[br * UU + u] = __ushort_as_bfloat16(hh);
            g_h_lo[br * UU + u] = __ushort_as_bfloat16(hl);
            if (t == TT - 1) out[br * UU + u] = h;
        }

        grid_barrier(sense ^= 1);   // 1024 flips: flag back to 0 for graph replay
    }
}

extern "C" void kernel_launch(void* const* d_in, const int* in_sizes, int n_in,
                              void* d_out, int out_size) {
    const float* x    = (const float*)d_in[0];
    const float* W    = (const float*)d_in[1];
    const float* R    = (const float*)d_in[2];
    const float* bias = (const float*)d_in[3];
    const float* h0   = (const float*)d_in[4];
    const float* c0   = (const float*)d_in[5];
    float* out = (float*)d_out;

    cudaFuncSetAttribute(lstm_gemm_x, cudaFuncAttributeMaxDynamicSharedMemorySize, G_SMEM);
    cudaFuncSetAttribute(lstm_recur,  cudaFuncAttributeMaxDynamicSharedMemorySize, R_SMEM);

    const int prep_total = PP * FI + PP * UU + PP + BB * UU;
    lstm_prep<<<(prep_total + 255) / 256, 256>>>(W, R, bias, h0);
    lstm_gemm_x<<<dim3(4096, 16), 256, G_SMEM>>>(x);
    lstm_recur<<<RC_CTAS, 256, R_SMEM>>>(c0, out);
}

// round 6
// speedup vs baseline: 8.6001x; 1.6941x over previous
#include <cuda_runtime.h>
#include <cuda_fp16.h>

typedef unsigned int u32;
typedef unsigned short u16;

#define TT 1024
#define BB 512
#define FI 128
#define UU 256
#define PP 1024        // 4*U permuted: P block b16=P>>4; c<8 -> i,f ; c>=8 -> o,g
#define RC_CTAS 128

// ---------------- device scratch ----------------
__device__ __half g_WT[PP * FI];          // W^T permuted [P][f]
__device__ __half g_RT[PP * UU];          // R^T permuted [P][k]
__device__ __half g_h[2][BB * UU];        // h state, double buffered
__device__ float g_bp[PP];
__device__ float g_xk[(size_t)TT * BB * PP];   // [(t*512+b)*1024 + P]
__device__ unsigned g_cnt[8 * 32];        // per-group barrier (128B padded)
__device__ unsigned g_flag[8 * 32];

// ---------------- helpers ----------------
__device__ __forceinline__ u32 s2u(const void* p) {
    u32 a;
    asm("{ .reg .u64 t; cvta.to.shared.u64 t, %1; cvt.u32.u64 %0, t; }" : "=r"(a) : "l"(p));
    return a;
}
__device__ __forceinline__ void ldsm4(u32 addr, u32* r) {
    asm volatile("ldmatrix.sync.aligned.m8n8.x4.shared.b16 {%0,%1,%2,%3}, [%4];"
                 : "=r"(r[0]), "=r"(r[1]), "=r"(r[2]), "=r"(r[3]) : "r"(addr));
}
__device__ __forceinline__ void mma16816(float* c, const u32* a, u32 b0, u32 b1) {
    asm volatile(
        "mma.sync.aligned.m16n8k16.row.col.f32.f16.f16.f32 "
        "{%0,%1,%2,%3},{%4,%5,%6,%7},{%8,%9},{%0,%1,%2,%3};"
        : "+f"(c[0]), "+f"(c[1]), "+f"(c[2]), "+f"(c[3])
        : "r"(a[0]), "r"(a[1]), "r"(a[2]), "r"(a[3]), "r"(b0), "r"(b1));
}
__device__ __forceinline__ float sig_fast(float x) {
    return __fdividef(1.0f, 1.0f + __expf(-x));
}
__device__ __forceinline__ float tanh_acc(float x) {
    return __fdividef(2.0f, 1.0f + __expf(-2.0f * x)) - 1.0f;
}
__device__ __forceinline__ int origcol(int P) {   // permuted col -> keras col
    int blk = P >> 4, c = P & 15;
    int u = 4 * blk + ((c >> 1) & 3);
    int g = ((c >> 3) << 1) | (c & 1);            // 0:i 1:f 2:o 3:g
    return g * UU + u;
}

// ================= prep =================
__global__ void lstm_prep(const float* __restrict__ W, const float* __restrict__ R,
                          const float* __restrict__ bias, const float* __restrict__ h0) {
    int i = blockIdx.x * blockDim.x + threadIdx.x;
    if (i < PP * FI) {
        int P = i >> 7, f = i & 127;
        g_WT[i] = __float2half_rn(W[f * PP + origcol(P)]);
    } else if (i < PP * FI + PP * UU) {
        int j = i - PP * FI;
        int P = j >> 8, k = j & 255;
        g_RT[j] = __float2half_rn(R[k * PP + origcol(P)]);
    } else if (i < PP * FI + PP * UU + PP) {
        int P = i - PP * FI - PP * UU;
        g_bp[P] = bias[origcol(P)];
    } else if (i < PP * FI + PP * UU + PP + BB * UU) {
        int j = i - PP * FI - PP * UU - PP;
        g_h[0][j] = __float2half_rn(h0[j]);
    }
}

// ================= phase 1: xk = x @ W (fp16 single pass) =================
// CTA tile 128 rows x 128 cols, K=128. grid (8, 4096): x-tile shared by 8 n-CTAs (L2 reuse).
#define G_A 0
#define G_B 34816          // A: 128 rows * 272B
#define G_SMEM (69632 + 32)

__global__ __launch_bounds__(256, 2) void lstm_gemm_x(const float* __restrict__ x) {
    extern __shared__ char sb[];
    const u32 sbase = s2u(sb);
    const int tid = threadIdx.x;
    const int w = tid >> 5, lane = tid & 31;
    const int n0 = blockIdx.x * 128;
    const int b = blockIdx.y >> 3;
    const int t0 = (blockIdx.y & 7) << 7;
    const int mchunk = w & 3;          // 4 x 32 rows
    const int nchunk = w >> 2;         // 2 x 64 cols
    const int q = lane & 3;

    // stage A: x rows -> fp16, stride 272B
    for (int it = 0; it < 16; it++) {
        int idx = tid + it * 256;                 // 4096 float4
        int row = idx >> 5, f4 = idx & 31;
        float4 v = *(const float4*)&x[((size_t)b * TT + t0 + row) * FI + f4 * 4];
        __half2 p0 = __floats2half2_rn(v.x, v.y);
        __half2 p1 = __floats2half2_rn(v.z, v.w);
        *(uint2*)(sb + G_A + row * 272 + f4 * 8) =
            make_uint2(*(u32*)&p0, *(u32*)&p1);
    }
    // stage B: W^T slice [128 n][128 k], stride 272B
    for (int it = 0; it < 8; it++) {
        int idx = tid + it * 256;                 // 2048 uint4
        int n = idx >> 4, ku = idx & 15;
        *(uint4*)(sb + G_B + n * 272 + ku * 16) =
            *(const uint4*)&g_WT[(n0 + n) * FI + ku * 8];
    }
    __syncthreads();

    const int rA = mchunk * 32 + (lane & 7) + 8 * ((lane >> 3) & 1);
    const int cA = 8 * ((lane >> 4) & 1);
    const u32 aAddr = sbase + G_A + rA * 272 + cA * 2;
    const int rB = nchunk * 64 + (lane & 7) + 8 * ((lane >> 4) & 1);
    const int cB = 8 * ((lane >> 3) & 1);
    const u32 bAddr = sbase + G_B + rB * 272 + cB * 2;

    float C[2][8][4];
#pragma unroll
    for (int m = 0; m < 2; m++)
#pragma unroll
        for (int n = 0; n < 8; n++)
#pragma unroll
            for (int r = 0; r < 4; r++) C[m][n][r] = 0.0f;

#pragma unroll
    for (int k = 0; k < 8; k++) {
        u32 a0[4], a1[4];
        ldsm4(aAddr + k * 32, a0);
        ldsm4(aAddr + 16 * 272 + k * 32, a1);
#pragma unroll
        for (int j = 0; j < 4; j++) {
            u32 bf[4];
            ldsm4(bAddr + j * 16 * 272 + k * 32, bf);
            mma16816(C[0][2 * j],     a0, bf[0], bf[1]);
            mma16816(C[0][2 * j + 1], a0, bf[2], bf[3]);
            mma16816(C[1][2 * j],     a1, bf[0], bf[1]);
            mma16816(C[1][2 * j + 1], a1, bf[2], bf[3]);
        }
    }

    // epilogue
#pragma unroll
    for (int mi = 0; mi < 4; mi++) {
        const int trow = t0 + mchunk * 32 + 8 * mi + (lane >> 2);
        float* dst = &g_xk[(((size_t)trow * BB) + b) * PP + n0 + nchunk * 64];
        const int m2 = mi >> 1, rr = (mi & 1) * 2;
#pragma unroll
        for (int nn = 0; nn < 8; nn++)
            *(float2*)(dst + 8 * nn + 2 * q) = make_float2(C[m2][nn][rr], C[m2][nn][rr + 1]);
    }
}

// ================= phase 2: persistent recurrence (fp16 single pass) =================
// 128 CTAs: mt = blk>>4 (8 groups x 64 batch rows), nt = blk&15 (64 P cols). K=256.
// B (R^T) fragments live in registers for all 1024 steps; A staged per step (32KB).
#define R_A 0
#define R_SMEM (33792 + 32)   // 64 rows * 528B

__device__ __forceinline__ void group_barrier(int mt, unsigned sense) {
    __syncthreads();
    if (threadIdx.x == 0) {
        __threadfence();
        unsigned arrived = atomicAdd(&g_cnt[mt * 32], 1);
        if (arrived == 15) {
            g_cnt[mt * 32] = 0;
            __threadfence();
            atomicExch(&g_flag[mt * 32], sense);
        } else {
            while (*(volatile unsigned*)&g_flag[mt * 32] != sense) { }
            __threadfence();
        }
    }
    __syncthreads();
}

__global__ __launch_bounds__(256, 1) void lstm_recur(const float* __restrict__ c0,
                                                     float* __restrict__ out) {
    extern __shared__ char sb[];
    const u32 sbase = s2u(sb);
    const int tid = threadIdx.x;
    const int w = tid >> 5, lane = tid & 31;
    const int mt = blockIdx.x >> 4;
    const int b_base = mt * 64;
    const int nt = blockIdx.x & 15;
    const int n0 = nt * 64;
    const int mchunk = w & 1;          // 2 x 32 rows
    const int nchunk = w >> 1;         // 4 x 16 cols
    const int q = lane & 3;

    // lane addresses (A/B share the smem region layout: stride 528B)
    const int rA = mchunk * 32 + (lane & 7) + 8 * ((lane >> 3) & 1);
    const int cA = 8 * ((lane >> 4) & 1);
    const u32 aAddr = sbase + R_A + rA * 528 + cA * 2;
    const int rB = nchunk * 16 + (lane & 7) + 8 * ((lane >> 4) & 1);
    const int cB = 8 * ((lane >> 3) & 1);
    const u32 bAddr = sbase + R_A + rB * 528 + cB * 2;

    // stage R^T slice into the A region, load fragments to regs, then free it
    for (int it = 0; it < 8; it++) {
        int idx = tid + it * 256;              // 2048 uint4
        int n = idx >> 5, ku = idx & 31;
        *(uint4*)(sb + R_A + n * 528 + ku * 16) =
            *(const uint4*)&g_RT[(n0 + n) * UU + ku * 8];
    }
    __syncthreads();
    u32 bh[16][4];
#pragma unroll
    for (int k = 0; k < 16; k++) ldsm4(bAddr + k * 32, bh[k]);
    __syncthreads();

    // thread owns all 4 gates of unit u for 4 batch rows
    const int B16 = nt * 4 + nchunk;
    const int u = 4 * B16 + q;
    const int row_l = lane >> 2;
    float c_reg[4];
#pragma unroll
    for (int mi = 0; mi < 4; mi++)
        c_reg[mi] = c0[(b_base + mchunk * 32 + 8 * mi + row_l) * UU + u];
    const float2 b_if = *(const float2*)&g_bp[16 * B16 + 2 * q];
    const float2 b_og = *(const float2*)&g_bp[16 * B16 + 8 + 2 * q];

    unsigned sense = 0;

    for (int t = 0; t < TT; t++) {
        // prefetch xk first (consumed after the mma loop; hides DRAM latency)
        float2 xk_if[4], xk_og[4];
#pragma unroll
        for (int mi = 0; mi < 4; mi++) {
            const float* xp = &g_xk[(((size_t)t * BB) + b_base + mchunk * 32 + 8 * mi + row_l) * PP
                                    + 16 * B16];
            xk_if[mi] = *(const float2*)(xp + 2 * q);
            xk_og[mi] = *(const float2*)(xp + 8 + 2 * q);
        }

        // stage h (fp16, 32KB) from buffer t&1
        const __half* hsrc = g_h[t & 1];
        for (int it = 0; it < 8; it++) {
            int idx = tid + it * 256;
            int r = idx >> 5, ku = idx & 31;
            *(uint4*)(sb + R_A + r * 528 + ku * 16) =
                *(const uint4*)&hsrc[(b_base + r) * UU + ku * 8];
        }
        __syncthreads();

        float C[2][2][4];
#pragma unroll
        for (int m = 0; m < 2; m++)
#pragma unroll
            for (int n = 0; n < 2; n++)
#pragma unroll
                for (int r = 0; r < 4; r++) C[m][n][r] = 0.0f;

#pragma unroll
        for (int k = 0; k < 16; k++) {
            u32 a0[4], a1[4];
            ldsm4(aAddr + k * 32, a0);
            ldsm4(aAddr + 16 * 528 + k * 32, a1);
            mma16816(C[0][0], a0, bh[k][0], bh[k][1]);
            mma16816(C[0][1], a0, bh[k][2], bh[k][3]);
            mma16816(C[1][0], a1, bh[k][0], bh[k][1]);
            mma16816(C[1][1], a1, bh[k][2], bh[k][3]);
        }

        // gates
        __half* hdst = g_h[(t + 1) & 1];
#pragma unroll
        for (int mi = 0; mi < 4; mi++) {
            const int m2 = mi >> 1, rr = (mi & 1) * 2;
            const float zi = C[m2][0][rr]     + xk_if[mi].x + b_if.x;
            const float zf = C[m2][0][rr + 1] + xk_if[mi].y + b_if.y;
            const float zo = C[m2][1][rr]     + xk_og[mi].x + b_og.x;
            const float zg = C[m2][1][rr + 1] + xk_og[mi].y + b_og.y;
            const float ig = sig_fast(zi);
            const float fg = sig_fast(zf);
            const float og = sig_fast(zo);
            const float gg = tanh_acc(zg);
            const float c = fmaf(fg, c_reg[mi], ig * gg);
            c_reg[mi] = c;
            const float h = og * tanh_acc(c);
            const int br = b_base + mchunk * 32 + 8 * mi + row_l;
            hdst[br * UU + u] = __float2half_rn(h);
            if (t == TT - 1) out[br * UU + u] = h;
        }

        group_barrier(mt, sense ^= 1);   // 1024 flips -> flag returns to 0 for graph replay
    }

    // mild cleanup sync not needed: per-group state already restored
}

extern "C" void kernel_launch(void* const* d_in, const int* in_sizes, int n_in,
                              void* d_out, int out_size) {
    const float* x    = (const float*)d_in[0];
    const float* W    = (const float*)d_in[1];
    const float* R    = (const float*)d_in[2];
    const float* bias = (const float*)d_in[3];
    const float* h0   = (const float*)d_in[4];
    const float* c0   = (const float*)d_in[5];
    float* out = (float*)d_out;

    cudaFuncSetAttribute(lstm_gemm_x, cudaFuncAttributeMaxDynamicSharedMemorySize, G_SMEM);
    cudaFuncSetAttribute(lstm_recur,  cudaFuncAttributeMaxDynamicSharedMemorySize, R_SMEM);

    const int prep_total = PP * FI + PP * UU + PP + BB * UU;
    lstm_prep<<<(prep_total + 255) / 256, 256>>>(W, R, bias, h0);
    lstm_gemm_x<<<dim3(8, 4096), 256, G_SMEM>>>(x);
    lstm_recur<<<RC_CTAS, 256, R_SMEM>>>(c0, out);
}